// round 15
// baseline (speedup 1.0000x reference)
#include <cuda_runtime.h>
#include <math.h>

#define B_   32
#define T_   1000
#define F_   80
#define H_   1024
#define HH_  2048
#define NBLK 128
#define EPSV 1e-5f

typedef unsigned long long ull;

// ---------------- scratch (static device globals; no allocation) ----------------
__device__ float  g_w[65536000];              // [32000][2048]
__device__ float  g_hs1[32768000];            // [32000][1024]
__device__ float  g_hT2[2][H_ * B_];          // double-buffered transposed h [parity][k][i]
__device__ float  g_colsum[HH_];
__device__ float  g_colsq[HH_];
__device__ float  g_scale[HH_];
__device__ float  g_shift[HH_];
__device__ __align__(16) float2 g_acc[T_][B_];  // t-indexed LN stats accumulators (S,Q)
__device__ unsigned g_cnt[2];                 // [0]=stats arrivals, [1]=h arrivals (monotonic)

// ---------------- helpers ----------------
union F4U { float4 f; ulonglong2 u; };

__device__ __forceinline__ void fma2(ull& d, ull a, ull b) {
    asm("fma.rn.f32x2 %0, %1, %2, %0;" : "+l"(d) : "l"(a), "l"(b));
}
__device__ __forceinline__ ull pack2(float v) {
    ull r;
    asm("mov.b64 %0, {%1, %1};" : "=l"(r) : "f"(v));
    return r;
}
__device__ __forceinline__ float ulo(ull v) { return __uint_as_float((unsigned)v); }
__device__ __forceinline__ float uhi(ull v) { return __uint_as_float((unsigned)(v >> 32)); }

__device__ __forceinline__ unsigned ld_acq(const unsigned* p) {
    unsigned v;
    asm volatile("ld.acquire.gpu.global.u32 %0, [%1];" : "=r"(v) : "l"(p));
    return v;
}
__device__ __forceinline__ void red_release(unsigned* p) {
    asm volatile("red.release.gpu.global.add.u32 [%0], 1;" :: "l"(p) : "memory");
}
__device__ __forceinline__ void red_addf(float* p, float v) {
    asm volatile("red.relaxed.gpu.global.add.f32 [%0], %1;" :: "l"(p), "f"(v) : "memory");
}

// ---------------- SGEMM (NT, f32x2 reg-packed, double-buffered): N=2048 ----------------
__global__ void __launch_bounds__(256)
sgemm_nt(const float* __restrict__ A, const float* __restrict__ Bm,
         float* __restrict__ C, int K)
{
    __shared__ float As[2][8][128];
    __shared__ float Bs[2][8][128];
    const int tid  = threadIdx.x;
    const int m0   = blockIdx.y * 128;
    const int n0   = blockIdx.x * 128;
    const int lrow = tid >> 1;
    const int lk4  = (tid & 1) * 4;
    const int tx   = tid & 15, ty = tid >> 4;
    const float* Ap = A  + (size_t)(m0 + lrow) * K + lk4;
    const float* Bp = Bm + (size_t)(n0 + lrow) * K + lk4;

    ull acc[8][4];
    #pragma unroll
    for (int i = 0; i < 8; i++)
        #pragma unroll
        for (int j = 0; j < 4; j++) acc[i][j] = 0ull;

    const int niter = K >> 3;
    float4 av = *(const float4*)(Ap);
    float4 bv = *(const float4*)(Bp);
    As[0][lk4 + 0][lrow] = av.x; As[0][lk4 + 1][lrow] = av.y;
    As[0][lk4 + 2][lrow] = av.z; As[0][lk4 + 3][lrow] = av.w;
    Bs[0][lk4 + 0][lrow] = bv.x; Bs[0][lk4 + 1][lrow] = bv.y;
    Bs[0][lk4 + 2][lrow] = bv.z; Bs[0][lk4 + 3][lrow] = bv.w;
    __syncthreads();

    for (int it = 0; it < niter; ++it) {
        const int s = it & 1;
        if (it + 1 < niter) {
            av = *(const float4*)(Ap + (it + 1) * 8);
            bv = *(const float4*)(Bp + (it + 1) * 8);
        }
        #pragma unroll
        for (int kk = 0; kk < 8; kk++) {
            F4U a0, a1, b0, b1;
            a0.f = *(const float4*)&As[s][kk][ty * 8];
            a1.f = *(const float4*)&As[s][kk][ty * 8 + 4];
            b0.f = *(const float4*)&Bs[s][kk][tx * 8];
            b1.f = *(const float4*)&Bs[s][kk][tx * 8 + 4];
            ull ap[8];
            ap[0] = pack2(a0.f.x); ap[1] = pack2(a0.f.y);
            ap[2] = pack2(a0.f.z); ap[3] = pack2(a0.f.w);
            ap[4] = pack2(a1.f.x); ap[5] = pack2(a1.f.y);
            ap[6] = pack2(a1.f.z); ap[7] = pack2(a1.f.w);
            ull bp[4] = {b0.u.x, b0.u.y, b1.u.x, b1.u.y};
            #pragma unroll
            for (int i = 0; i < 8; i++)
                #pragma unroll
                for (int j = 0; j < 4; j++)
                    fma2(acc[i][j], ap[i], bp[j]);
        }
        if (it + 1 < niter) {
            const int ns = s ^ 1;
            As[ns][lk4 + 0][lrow] = av.x; As[ns][lk4 + 1][lrow] = av.y;
            As[ns][lk4 + 2][lrow] = av.z; As[ns][lk4 + 3][lrow] = av.w;
            Bs[ns][lk4 + 0][lrow] = bv.x; Bs[ns][lk4 + 1][lrow] = bv.y;
            Bs[ns][lk4 + 2][lrow] = bv.z; Bs[ns][lk4 + 3][lrow] = bv.w;
            __syncthreads();
        }
    }
    #pragma unroll
    for (int i = 0; i < 8; i++) {
        float* Cp = C + (size_t)(m0 + ty * 8 + i) * HH_ + n0 + tx * 8;
        ulonglong2 s0; s0.x = acc[i][0]; s0.y = acc[i][1];
        ulonglong2 s1; s1.x = acc[i][2]; s1.y = acc[i][3];
        *(ulonglong2*)Cp       = s0;
        *(ulonglong2*)(Cp + 4) = s1;
    }
}

// ---------------- BatchNorm column stats over 32000 rows ----------------
__global__ void __launch_bounds__(256)
bn_stats(const float* __restrict__ w)
{
    int col = blockIdx.x * 256 + threadIdx.x;
    size_t r0 = (size_t)blockIdx.y * 1000;
    float s = 0.0f, q = 0.0f;
    const float* p = w + r0 * HH_ + col;
    #pragma unroll 4
    for (int r = 0; r < 1000; r++) {
        float v = p[(size_t)r * HH_];
        s += v; q += v * v;
    }
    atomicAdd(&g_colsum[col], s);
    atomicAdd(&g_colsq[col], q);
}

__global__ void __launch_bounds__(256)
bn_finalize(const float* __restrict__ gamma, const float* __restrict__ beta)
{
    int c = blockIdx.x * 256 + threadIdx.x;
    float mean = g_colsum[c] * (1.0f / 32000.0f);
    float var  = g_colsq[c] * (1.0f / 32000.0f) - mean * mean;
    float sc = gamma[c] * rsqrtf(var + EPSV);
    g_scale[c] = sc;
    g_shift[c] = beta[c] - mean * sc;
}

// ---------------- Persistent LiGRU recurrence (L2-atomic LN stats) ----------------
// SMEM floats:
//   Us    [1024][16]         @ 0       (16384, un-duplicated)
//   red   [16][512]          @ 16384   (8192)
//   uhbuf [512]              @ 24576
//   scs   [16]               @ 25088
//   shs   [16]               @ 25104   -> 25120 floats = 100480 B
#define REC_SMEM_FLOATS 25120

__global__ void __launch_bounds__(512, 1)
rec_kernel(const float* __restrict__ w, const float* __restrict__ U,
           float* __restrict__ hs_out)
{
    extern __shared__ float sm[];
    float* Us    = sm;
    float* red   = sm + 16384;
    float* uhbuf = sm + 24576;
    float* scs   = sm + 25088;
    float* shs   = sm + 25104;

    const int tid = threadIdx.x;
    const int b   = blockIdx.x;
    const int cb  = b * 8;

    // One-time: U slice transposed (Us[k][jj]); fold BN scale/shift
    for (int idx = tid; idx < 16 * 1024; idx += 512) {
        int jj = idx >> 10, k = idx & 1023;
        int urow = (jj < 8) ? (cb + jj) : (H_ + cb + jj - 8);
        Us[k * 16 + jj] = U[(size_t)urow * H_ + k];
    }
    if (tid < 16) {
        int col = (tid < 8) ? (cb + tid) : (H_ + cb + tid - 8);
        scs[tid] = g_scale[col];
        shs[tid] = g_shift[col];
    }
    __syncthreads();

    const int warp  = tid >> 5, lane = tid & 31;
    const int i0    = (lane & 7) * 4;     // 4 batch rows (2 f32x2 pairs)
    const int jj0   = (lane >> 3) * 4;    // 4 gate cols
    const int kbase = warp * 64;          // K segment per warp

    const int ui = tid >> 3;              // update/stats batch row (threads < 256)
    const int uj = tid & 7;               // update h-col within block

    float hreg = 0.0f;

    const float* useg = Us + kbase * 16 + jj0;

    for (int t = 0; t < T_; ++t) {
        const int par = t & 1;

        // -- prefetch this step's w (issued before the h-wait) --
        float wa_raw = 0.0f, wz_raw = 0.0f;
        if (tid < 256) {
            size_t wrow = (size_t)(ui * T_ + t) * HH_;
            wa_raw = __ldg(w + wrow + cb + uj);
            wz_raw = __ldg(w + wrow + H_ + cb + uj);
        }

        // -- wait: all blocks published h(t-1) (counter is monotonic; t=0 passes) --
        if (tid == 0 && t > 0) {
            const unsigned tgt = (unsigned)t * NBLK;
            while (ld_acq(&g_cnt[1]) < tgt) { }
        }
        __syncthreads();

        // -- per-warp partial GEMM over K segment (f32x2; U deduped, reg-packed) --
        const float* hseg = g_hT2[par ^ 1] + kbase * B_ + i0;
        ull acc[2][4];
        #pragma unroll
        for (int p = 0; p < 2; p++)
            #pragma unroll
            for (int j = 0; j < 4; j++) acc[p][j] = 0ull;

        F4U hv0[4], hv1[4];
        #pragma unroll
        for (int u = 0; u < 4; u++)
            hv0[u].f = __ldcg((const float4*)(hseg + u * B_));

        #pragma unroll
        for (int g = 0; g < 16; ++g) {
            F4U* hc = (g & 1) ? hv1 : hv0;
            F4U* hn = (g & 1) ? hv0 : hv1;
            if (g < 15) {
                #pragma unroll
                for (int u = 0; u < 4; u++)
                    hn[u].f = __ldcg((const float4*)(hseg + ((g + 1) * 4 + u) * B_));
            }
            #pragma unroll
            for (int u = 0; u < 4; u++) {
                float4 uv = *(const float4*)(useg + (g * 4 + u) * 16);
                ull ux = pack2(uv.x), uy = pack2(uv.y);
                ull uz = pack2(uv.z), uw = pack2(uv.w);
                fma2(acc[0][0], hc[u].u.x, ux);
                fma2(acc[1][0], hc[u].u.y, ux);
                fma2(acc[0][1], hc[u].u.x, uy);
                fma2(acc[1][1], hc[u].u.y, uy);
                fma2(acc[0][2], hc[u].u.x, uz);
                fma2(acc[1][2], hc[u].u.y, uz);
                fma2(acc[0][3], hc[u].u.x, uw);
                fma2(acc[1][3], hc[u].u.y, uw);
            }
        }
        {
            float4 r0 = make_float4(ulo(acc[0][0]), ulo(acc[0][1]), ulo(acc[0][2]), ulo(acc[0][3]));
            float4 r1 = make_float4(uhi(acc[0][0]), uhi(acc[0][1]), uhi(acc[0][2]), uhi(acc[0][3]));
            float4 r2 = make_float4(ulo(acc[1][0]), ulo(acc[1][1]), ulo(acc[1][2]), ulo(acc[1][3]));
            float4 r3 = make_float4(uhi(acc[1][0]), uhi(acc[1][1]), uhi(acc[1][2]), uhi(acc[1][3]));
            float* rp = red + warp * 512 + i0 * 16 + jj0;
            *(float4*)(rp)      = r0;
            *(float4*)(rp + 16) = r1;
            *(float4*)(rp + 32) = r2;
            *(float4*)(rp + 48) = r3;
        }
        __syncthreads();

        // -- cross-warp K reduction (dual chains) + LN partials -> L2 atomic aggregate --
        {
            float v0 = red[tid];
            float v1 = red[512 + tid];
            #pragma unroll
            for (int wv = 2; wv < 16; wv += 2) {
                v0 += red[wv * 512 + tid];
                v1 += red[(wv + 1) * 512 + tid];
            }
            float v = v0 + v1;
            uhbuf[tid] = v;
            float S = v, Q = v * v;
            #pragma unroll
            for (int d = 8; d >= 1; d >>= 1) {
                S += __shfl_xor_sync(0xffffffffu, S, d, 16);
                Q += __shfl_xor_sync(0xffffffffu, Q, d, 16);
            }
            if ((tid & 15) == 0) {
                float* ap = (float*)&g_acc[t][tid >> 4];
                red_addf(ap,     S);
                red_addf(ap + 1, Q);
            }
        }
        __syncthreads();

        // -- stats arrival (release RMW) + wait --
        if (tid == 0) {
            red_release(&g_cnt[0]);
            const unsigned tgt = (unsigned)(t + 1) * NBLK;
            while (ld_acq(&g_cnt[0]) < tgt) { }
        }
        __syncthreads();

        // -- gate + h update (stats = one 8B read from L2 accumulator) --
        float hnew = 0.0f;
        if (tid < 256) {
            float2 sq = __ldcg(&g_acc[t][ui]);
            float mean = sq.x * (1.0f / 2048.0f);
            float var  = sq.y * (1.0f / 2048.0f) - mean * mean;
            float rstd = rsqrtf(var + EPSV);

            float an = (uhbuf[ui * 16 + uj]     - mean) * rstd;
            float zn = (uhbuf[ui * 16 + 8 + uj] - mean) * rstd;
            float wa = wa_raw * scs[uj]     + shs[uj];
            float wz = wz_raw * scs[8 + uj] + shs[8 + uj];
            float a  = wa + an;
            float zx = wz + zn;
            float z  = 1.0f / (1.0f + __expf(-zx));
            hnew = z * hreg + (1.0f - z) * fmaxf(a, 0.0f);
            hreg = hnew;
            g_hT2[par][(cb + uj) * B_ + ui] = hnew;
        }
        __syncthreads();

        // -- publish h arrival (release RMW) --
        if (tid == 0) {
            red_release(&g_cnt[1]);
        }

        // -- hs_out DRAM store off the critical path --
        if (tid < 256) {
            hs_out[(size_t)(ui * T_ + t) * H_ + cb + uj] = hnew;
        }
    }
}

// ---------------- launch ----------------
extern "C" void kernel_launch(void* const* d_in, const int* in_sizes, int n_in,
                              void* d_out, int out_size)
{
    const float* x  = (const float*)d_in[0];
    const float* W1 = (const float*)d_in[1];
    const float* U1 = (const float*)d_in[2];
    const float* g1 = (const float*)d_in[3];
    const float* b1 = (const float*)d_in[4];
    const float* W2 = (const float*)d_in[5];
    const float* U2 = (const float*)d_in[6];
    const float* g2 = (const float*)d_in[7];
    const float* b2 = (const float*)d_in[8];
    float* out = (float*)d_out;

    float *w_buf, *hs1, *csum, *csq, *hT2, *accp;
    unsigned* cnt;
    cudaGetSymbolAddress((void**)&w_buf, g_w);
    cudaGetSymbolAddress((void**)&hs1,   g_hs1);
    cudaGetSymbolAddress((void**)&csum,  g_colsum);
    cudaGetSymbolAddress((void**)&csq,   g_colsq);
    cudaGetSymbolAddress((void**)&hT2,   g_hT2);
    cudaGetSymbolAddress((void**)&accp,  g_acc);
    cudaGetSymbolAddress((void**)&cnt,   g_cnt);

    cudaFuncSetAttribute(rec_kernel, cudaFuncAttributeMaxDynamicSharedMemorySize,
                         REC_SMEM_FLOATS * 4);

    dim3 gproj(16, 250);

    // ---- Layer 1 ----
    sgemm_nt<<<gproj, 256>>>(x, W1, w_buf, F_);
    cudaMemsetAsync(csum, 0, HH_ * 4);
    cudaMemsetAsync(csq,  0, HH_ * 4);
    bn_stats<<<dim3(8, 32), 256>>>(w_buf);
    bn_finalize<<<8, 256>>>(g1, b1);
    cudaMemsetAsync(hT2, 0, 2 * H_ * B_ * 4);
    cudaMemsetAsync(cnt, 0, 2 * 4);
    cudaMemsetAsync(accp, 0, T_ * B_ * 8);
    rec_kernel<<<NBLK, 512, REC_SMEM_FLOATS * 4>>>(w_buf, U1, hs1);

    // ---- Layer 2 ----
    sgemm_nt<<<gproj, 256>>>(hs1, W2, w_buf, H_);
    cudaMemsetAsync(csum, 0, HH_ * 4);
    cudaMemsetAsync(csq,  0, HH_ * 4);
    bn_stats<<<dim3(8, 32), 256>>>(w_buf);
    bn_finalize<<<8, 256>>>(g2, b2);
    cudaMemsetAsync(hT2, 0, 2 * H_ * B_ * 4);
    cudaMemsetAsync(cnt, 0, 2 * 4);
    cudaMemsetAsync(accp, 0, T_ * B_ * 8);
    rec_kernel<<<NBLK, 512, REC_SMEM_FLOATS * 4>>>(w_buf, U2, out);

    (void)in_sizes; (void)n_in; (void)out_size;
}

// round 16
// speedup vs baseline: 1.1310x; 1.1310x over previous
#include <cuda_runtime.h>
#include <math.h>

#define B_   32
#define T_   1000
#define F_   80
#define H_   1024
#define HH_  2048
#define NBLK 128
#define EPSV 1e-5f

typedef unsigned long long ull;

// ---------------- scratch (static device globals; no allocation) ----------------
__device__ float  g_w[65536000];              // [32000][2048]
__device__ float  g_hs1[32768000];            // [32000][1024]
__device__ float  g_hT2[2][H_ * B_];          // double-buffered transposed h [parity][k][i]
__device__ float  g_colsum[HH_];
__device__ float  g_colsq[HH_];
__device__ float  g_scale[HH_];
__device__ float  g_shift[HH_];
__device__ __align__(16) float2 g_pp[2][B_ * NBLK];  // [parity][i*NBLK+b] (sum, sumsq)
__device__ unsigned g_cnt[2];                 // [0]=stats arrivals, [1]=h arrivals (monotonic)

// ---------------- helpers ----------------
union F4U { float4 f; ulonglong2 u; };

__device__ __forceinline__ void fma2(ull& d, ull a, ull b) {
    asm("fma.rn.f32x2 %0, %1, %2, %0;" : "+l"(d) : "l"(a), "l"(b));
}
__device__ __forceinline__ ull pack2(float v) {
    ull r;
    asm("mov.b64 %0, {%1, %1};" : "=l"(r) : "f"(v));
    return r;
}
__device__ __forceinline__ float ulo(ull v) { return __uint_as_float((unsigned)v); }
__device__ __forceinline__ float uhi(ull v) { return __uint_as_float((unsigned)(v >> 32)); }

__device__ __forceinline__ unsigned ld_acq(const unsigned* p) {
    unsigned v;
    asm volatile("ld.acquire.gpu.global.u32 %0, [%1];" : "=r"(v) : "l"(p));
    return v;
}
__device__ __forceinline__ void red_release(unsigned* p) {
    asm volatile("red.release.gpu.global.add.u32 [%0], 1;" :: "l"(p) : "memory");
}

// ---------------- SGEMM (NT, f32x2 reg-packed, double-buffered): N=2048 ----------------
__global__ void __launch_bounds__(256)
sgemm_nt(const float* __restrict__ A, const float* __restrict__ Bm,
         float* __restrict__ C, int K)
{
    __shared__ float As[2][8][128];
    __shared__ float Bs[2][8][128];
    const int tid  = threadIdx.x;
    const int m0   = blockIdx.y * 128;
    const int n0   = blockIdx.x * 128;
    const int lrow = tid >> 1;
    const int lk4  = (tid & 1) * 4;
    const int tx   = tid & 15, ty = tid >> 4;
    const float* Ap = A  + (size_t)(m0 + lrow) * K + lk4;
    const float* Bp = Bm + (size_t)(n0 + lrow) * K + lk4;

    ull acc[8][4];
    #pragma unroll
    for (int i = 0; i < 8; i++)
        #pragma unroll
        for (int j = 0; j < 4; j++) acc[i][j] = 0ull;

    const int niter = K >> 3;
    float4 av = *(const float4*)(Ap);
    float4 bv = *(const float4*)(Bp);
    As[0][lk4 + 0][lrow] = av.x; As[0][lk4 + 1][lrow] = av.y;
    As[0][lk4 + 2][lrow] = av.z; As[0][lk4 + 3][lrow] = av.w;
    Bs[0][lk4 + 0][lrow] = bv.x; Bs[0][lk4 + 1][lrow] = bv.y;
    Bs[0][lk4 + 2][lrow] = bv.z; Bs[0][lk4 + 3][lrow] = bv.w;
    __syncthreads();

    for (int it = 0; it < niter; ++it) {
        const int s = it & 1;
        if (it + 1 < niter) {
            av = *(const float4*)(Ap + (it + 1) * 8);
            bv = *(const float4*)(Bp + (it + 1) * 8);
        }
        #pragma unroll
        for (int kk = 0; kk < 8; kk++) {
            F4U a0, a1, b0, b1;
            a0.f = *(const float4*)&As[s][kk][ty * 8];
            a1.f = *(const float4*)&As[s][kk][ty * 8 + 4];
            b0.f = *(const float4*)&Bs[s][kk][tx * 8];
            b1.f = *(const float4*)&Bs[s][kk][tx * 8 + 4];
            ull ap[8];
            ap[0] = pack2(a0.f.x); ap[1] = pack2(a0.f.y);
            ap[2] = pack2(a0.f.z); ap[3] = pack2(a0.f.w);
            ap[4] = pack2(a1.f.x); ap[5] = pack2(a1.f.y);
            ap[6] = pack2(a1.f.z); ap[7] = pack2(a1.f.w);
            ull bp[4] = {b0.u.x, b0.u.y, b1.u.x, b1.u.y};
            #pragma unroll
            for (int i = 0; i < 8; i++)
                #pragma unroll
                for (int j = 0; j < 4; j++)
                    fma2(acc[i][j], ap[i], bp[j]);
        }
        if (it + 1 < niter) {
            const int ns = s ^ 1;
            As[ns][lk4 + 0][lrow] = av.x; As[ns][lk4 + 1][lrow] = av.y;
            As[ns][lk4 + 2][lrow] = av.z; As[ns][lk4 + 3][lrow] = av.w;
            Bs[ns][lk4 + 0][lrow] = bv.x; Bs[ns][lk4 + 1][lrow] = bv.y;
            Bs[ns][lk4 + 2][lrow] = bv.z; Bs[ns][lk4 + 3][lrow] = bv.w;
            __syncthreads();
        }
    }
    #pragma unroll
    for (int i = 0; i < 8; i++) {
        float* Cp = C + (size_t)(m0 + ty * 8 + i) * HH_ + n0 + tx * 8;
        ulonglong2 s0; s0.x = acc[i][0]; s0.y = acc[i][1];
        ulonglong2 s1; s1.x = acc[i][2]; s1.y = acc[i][3];
        *(ulonglong2*)Cp       = s0;
        *(ulonglong2*)(Cp + 4) = s1;
    }
}

// ---------------- BatchNorm column stats over 32000 rows ----------------
__global__ void __launch_bounds__(256)
bn_stats(const float* __restrict__ w)
{
    int col = blockIdx.x * 256 + threadIdx.x;
    size_t r0 = (size_t)blockIdx.y * 1000;
    float s = 0.0f, q = 0.0f;
    const float* p = w + r0 * HH_ + col;
    #pragma unroll 4
    for (int r = 0; r < 1000; r++) {
        float v = p[(size_t)r * HH_];
        s += v; q += v * v;
    }
    atomicAdd(&g_colsum[col], s);
    atomicAdd(&g_colsq[col], q);
}

__global__ void __launch_bounds__(256)
bn_finalize(const float* __restrict__ gamma, const float* __restrict__ beta)
{
    int c = blockIdx.x * 256 + threadIdx.x;
    float mean = g_colsum[c] * (1.0f / 32000.0f);
    float var  = g_colsq[c] * (1.0f / 32000.0f) - mean * mean;
    float sc = gamma[c] * rsqrtf(var + EPSV);
    g_scale[c] = sc;
    g_shift[c] = beta[c] - mean * sc;
}

// ---------------- Persistent LiGRU recurrence (R14 + padded red) ----------------
// SMEM floats:
//   Us    [1024][16]          @ 0       (16384, un-duplicated)
//   red   [16][640]           @ 16384   (10240, rows padded to stride 20)
//   uhbuf [512]               @ 26624
//   scs   [16]                @ 27136
//   shs   [16]                @ 27152   -> 27168 floats = 108672 B
#define REC_SMEM_FLOATS 27168

__global__ void __launch_bounds__(512, 1)
rec_kernel(const float* __restrict__ w, const float* __restrict__ U,
           float* __restrict__ hs_out)
{
    extern __shared__ float sm[];
    float* Us    = sm;
    float* red   = sm + 16384;
    float* uhbuf = sm + 26624;
    float* scs   = sm + 27136;
    float* shs   = sm + 27152;

    const int tid = threadIdx.x;
    const int b   = blockIdx.x;
    const int cb  = b * 8;

    // One-time: U slice transposed (Us[k][jj]); fold BN scale/shift
    for (int idx = tid; idx < 16 * 1024; idx += 512) {
        int jj = idx >> 10, k = idx & 1023;
        int urow = (jj < 8) ? (cb + jj) : (H_ + cb + jj - 8);
        Us[k * 16 + jj] = U[(size_t)urow * H_ + k];
    }
    if (tid < 16) {
        int col = (tid < 8) ? (cb + tid) : (H_ + cb + tid - 8);
        scs[tid] = g_scale[col];
        shs[tid] = g_shift[col];
    }
    __syncthreads();

    const int warp  = tid >> 5, lane = tid & 31;
    const int i0    = (lane & 7) * 4;     // 4 batch rows (2 f32x2 pairs)
    const int jj0   = (lane >> 3) * 4;    // 4 gate cols
    const int kbase = warp * 64;          // K segment per warp

    const int ui = tid >> 3;              // update/stats batch row (threads < 256)
    const int uj = tid & 7;               // update h-col within block

    float hreg = 0.0f;

    const float* useg = Us + kbase * 16 + jj0;
    const int redoff = (tid >> 4) * 20 + (tid & 15);   // padded read offset

    for (int t = 0; t < T_; ++t) {
        const int par = t & 1;

        // -- prefetch this step's w (issued before the h-wait) --
        float wa_raw = 0.0f, wz_raw = 0.0f;
        if (tid < 256) {
            size_t wrow = (size_t)(ui * T_ + t) * HH_;
            wa_raw = __ldg(w + wrow + cb + uj);
            wz_raw = __ldg(w + wrow + H_ + cb + uj);
        }

        // -- wait: all blocks published h(t-1) (counter is monotonic; t=0 passes) --
        if (tid == 0 && t > 0) {
            const unsigned tgt = (unsigned)t * NBLK;
            while (ld_acq(&g_cnt[1]) < tgt) { }
        }
        __syncthreads();

        // -- per-warp partial GEMM over K segment (f32x2; U deduped, reg-packed) --
        const float* hseg = g_hT2[par ^ 1] + kbase * B_ + i0;
        ull acc[2][4];
        #pragma unroll
        for (int p = 0; p < 2; p++)
            #pragma unroll
            for (int j = 0; j < 4; j++) acc[p][j] = 0ull;

        F4U hv0[4], hv1[4];
        #pragma unroll
        for (int u = 0; u < 4; u++)
            hv0[u].f = __ldcg((const float4*)(hseg + u * B_));

        #pragma unroll
        for (int g = 0; g < 16; ++g) {
            F4U* hc = (g & 1) ? hv1 : hv0;
            F4U* hn = (g & 1) ? hv0 : hv1;
            if (g < 15) {
                #pragma unroll
                for (int u = 0; u < 4; u++)
                    hn[u].f = __ldcg((const float4*)(hseg + ((g + 1) * 4 + u) * B_));
            }
            #pragma unroll
            for (int u = 0; u < 4; u++) {
                float4 uv = *(const float4*)(useg + (g * 4 + u) * 16);
                ull ux = pack2(uv.x), uy = pack2(uv.y);
                ull uz = pack2(uv.z), uw = pack2(uv.w);
                fma2(acc[0][0], hc[u].u.x, ux);
                fma2(acc[1][0], hc[u].u.y, ux);
                fma2(acc[0][1], hc[u].u.x, uy);
                fma2(acc[1][1], hc[u].u.y, uy);
                fma2(acc[0][2], hc[u].u.x, uz);
                fma2(acc[1][2], hc[u].u.y, uz);
                fma2(acc[0][3], hc[u].u.x, uw);
                fma2(acc[1][3], hc[u].u.y, uw);
            }
        }
        {
            float4 r0 = make_float4(ulo(acc[0][0]), ulo(acc[0][1]), ulo(acc[0][2]), ulo(acc[0][3]));
            float4 r1 = make_float4(uhi(acc[0][0]), uhi(acc[0][1]), uhi(acc[0][2]), uhi(acc[0][3]));
            float4 r2 = make_float4(ulo(acc[1][0]), ulo(acc[1][1]), ulo(acc[1][2]), ulo(acc[1][3]));
            float4 r3 = make_float4(uhi(acc[1][0]), uhi(acc[1][1]), uhi(acc[1][2]), uhi(acc[1][3]));
            float* rp = red + warp * 640 + i0 * 20 + jj0;   // rows i0..i0+3, stride 20
            *(float4*)(rp)      = r0;
            *(float4*)(rp + 20) = r1;
            *(float4*)(rp + 40) = r2;
            *(float4*)(rp + 60) = r3;
        }
        __syncthreads();

        // -- cross-warp K reduction (dual chains for ILP) + LN partials --
        {
            float v0 = red[redoff];
            float v1 = red[640 + redoff];
            #pragma unroll
            for (int wv = 2; wv < 16; wv += 2) {
                v0 += red[wv * 640 + redoff];
                v1 += red[(wv + 1) * 640 + redoff];
            }
            float v = v0 + v1;
            uhbuf[tid] = v;
            float S = v, Q = v * v;
            #pragma unroll
            for (int d = 8; d >= 1; d >>= 1) {
                S += __shfl_xor_sync(0xffffffffu, S, d, 16);
                Q += __shfl_xor_sync(0xffffffffu, Q, d, 16);
            }
            if ((tid & 15) == 0) {
                g_pp[par][(tid >> 4) * NBLK + b] = make_float2(S, Q);
            }
        }
        __syncthreads();

        // -- stats arrival (release RMW) + wait --
        if (tid == 0) {
            red_release(&g_cnt[0]);
            const unsigned tgt = (unsigned)(t + 1) * NBLK;
            while (ld_acq(&g_cnt[0]) < tgt) { }
        }
        __syncthreads();

        // -- fused global stats reduce (float4 loads, dual chains) + gate + h update --
        float hnew = 0.0f;
        if (tid < 256) {
            const float4* pp4 = (const float4*)(g_pp[par] + ui * NBLK + uj * 16);
            float S0 = 0.f, Q0 = 0.f, S1 = 0.f, Q1 = 0.f;
            #pragma unroll
            for (int q = 0; q < 8; q += 2) {
                float4 va = __ldcg(pp4 + q);
                float4 vb = __ldcg(pp4 + q + 1);
                S0 += va.x + va.z; Q0 += va.y + va.w;
                S1 += vb.x + vb.z; Q1 += vb.y + vb.w;
            }
            float S = S0 + S1, Q = Q0 + Q1;
            #pragma unroll
            for (int d = 4; d >= 1; d >>= 1) {
                S += __shfl_xor_sync(0xffffffffu, S, d, 8);
                Q += __shfl_xor_sync(0xffffffffu, Q, d, 8);
            }
            float mean = S * (1.0f / 2048.0f);
            float var  = Q * (1.0f / 2048.0f) - mean * mean;
            float rstd = rsqrtf(var + EPSV);

            float an = (uhbuf[ui * 16 + uj]     - mean) * rstd;
            float zn = (uhbuf[ui * 16 + 8 + uj] - mean) * rstd;
            float wa = wa_raw * scs[uj]     + shs[uj];
            float wz = wz_raw * scs[8 + uj] + shs[8 + uj];
            float a  = wa + an;
            float zx = wz + zn;
            float z  = 1.0f / (1.0f + __expf(-zx));
            hnew = z * hreg + (1.0f - z) * fmaxf(a, 0.0f);
            hreg = hnew;
            g_hT2[par][(cb + uj) * B_ + ui] = hnew;
        }
        __syncthreads();

        // -- publish h arrival (release RMW) --
        if (tid == 0) {
            red_release(&g_cnt[1]);
        }

        // -- hs_out DRAM store off the critical path --
        if (tid < 256) {
            hs_out[(size_t)(ui * T_ + t) * H_ + cb + uj] = hnew;
        }
    }
}

// ---------------- launch ----------------
extern "C" void kernel_launch(void* const* d_in, const int* in_sizes, int n_in,
                              void* d_out, int out_size)
{
    const float* x  = (const float*)d_in[0];
    const float* W1 = (const float*)d_in[1];
    const float* U1 = (const float*)d_in[2];
    const float* g1 = (const float*)d_in[3];
    const float* b1 = (const float*)d_in[4];
    const float* W2 = (const float*)d_in[5];
    const float* U2 = (const float*)d_in[6];
    const float* g2 = (const float*)d_in[7];
    const float* b2 = (const float*)d_in[8];
    float* out = (float*)d_out;

    float *w_buf, *hs1, *csum, *csq, *hT2;
    unsigned* cnt;
    cudaGetSymbolAddress((void**)&w_buf, g_w);
    cudaGetSymbolAddress((void**)&hs1,   g_hs1);
    cudaGetSymbolAddress((void**)&csum,  g_colsum);
    cudaGetSymbolAddress((void**)&csq,   g_colsq);
    cudaGetSymbolAddress((void**)&hT2,   g_hT2);
    cudaGetSymbolAddress((void**)&cnt,   g_cnt);

    cudaFuncSetAttribute(rec_kernel, cudaFuncAttributeMaxDynamicSharedMemorySize,
                         REC_SMEM_FLOATS * 4);

    dim3 gproj(16, 250);

    // ---- Layer 1 ----
    sgemm_nt<<<gproj, 256>>>(x, W1, w_buf, F_);
    cudaMemsetAsync(csum, 0, HH_ * 4);
    cudaMemsetAsync(csq,  0, HH_ * 4);
    bn_stats<<<dim3(8, 32), 256>>>(w_buf);
    bn_finalize<<<8, 256>>>(g1, b1);
    cudaMemsetAsync(hT2, 0, 2 * H_ * B_ * 4);
    cudaMemsetAsync(cnt, 0, 2 * 4);
    rec_kernel<<<NBLK, 512, REC_SMEM_FLOATS * 4>>>(w_buf, U1, hs1);

    // ---- Layer 2 ----
    sgemm_nt<<<gproj, 256>>>(hs1, W2, w_buf, H_);
    cudaMemsetAsync(csum, 0, HH_ * 4);
    cudaMemsetAsync(csq,  0, HH_ * 4);
    bn_stats<<<dim3(8, 32), 256>>>(w_buf);
    bn_finalize<<<8, 256>>>(g2, b2);
    cudaMemsetAsync(hT2, 0, 2 * H_ * B_ * 4);
    cudaMemsetAsync(cnt, 0, 2 * 4);
    rec_kernel<<<NBLK, 512, REC_SMEM_FLOATS * 4>>>(w_buf, U2, out);

    (void)in_sizes; (void)n_in; (void)out_size;
}